// round 16
// baseline (speedup 1.0000x reference)
#include <cuda_runtime.h>
#include <cuda_bf16.h>
#include <math.h>
#include <stdint.h>

// ---------------- problem constants ----------------
#define BATCH 8
#define CHN 3
#define IMG 224
#define PATCH 16
#define GRID 14
#define NPATCH 196
#define SEQ 197
#define DIM 768
#define NHEAD 12
#define HDIM 64
#define NLAYER 12
#define TOPK 32
#define MLPDIM 3072
#define ATT_SCALE 0.125f

#define NROWS (BATCH*SEQ)           // 1576
#define NROWS_P (BATCH*NPATCH)      // 1568

#define NW_PATCH (DIM*DIM)
#define NW_QKV   (NLAYER*3*DIM*DIM)
#define NW_PROJ  (NLAYER*DIM*DIM)
#define NW_FC1   (NLAYER*MLPDIM*DIM)
#define NW_FC2   (NLAYER*DIM*MLPDIM)
#define OFF_PATCH 0
#define OFF_QKV   (OFF_PATCH + NW_PATCH)
#define OFF_PROJ  (OFF_QKV + NW_QKV)
#define OFF_FC1   (OFF_PROJ + NW_PROJ)
#define OFF_FC2   (OFF_FC1 + NW_FC1)
#define NW_TOTAL  (OFF_FC2 + NW_FC2)

// ---------------- scratch ----------------
__device__ float g_h  [BATCH*SEQ*DIM];
__device__ float g_qkv[BATCH*SEQ*3*DIM];
__device__ __nv_bfloat16 g_xnh [BATCH*SEQ*DIM];
__device__ __nv_bfloat16 g_xnl [BATCH*SEQ*DIM];
__device__ __nv_bfloat16 g_atth[BATCH*SEQ*DIM];
__device__ __nv_bfloat16 g_attl[BATCH*SEQ*DIM];
__device__ __nv_bfloat16 g_mlph[BATCH*SEQ*MLPDIM];
__device__ __nv_bfloat16 g_mlpl[BATCH*SEQ*MLPDIM];
__device__ __nv_bfloat16 g_wh[NW_TOTAL];
__device__ __nv_bfloat16 g_wl[NW_TOTAL];

// ---------------- helpers ----------------
__device__ __forceinline__ uint32_t smem_u32(const void* p) {
    uint32_t a;
    asm("{ .reg .u64 t; cvta.to.shared.u64 t, %1; cvt.u32.u64 %0, t; }" : "=r"(a) : "l"(p));
    return a;
}
__device__ __forceinline__ uint32_t pack_bf16(__nv_bfloat16 a, __nv_bfloat16 b) {
    return (uint32_t)__bfloat16_as_ushort(a) | ((uint32_t)__bfloat16_as_ushort(b) << 16);
}
__device__ __forceinline__ void split1(float v, __nv_bfloat16& h, __nv_bfloat16& l) {
    h = __float2bfloat16(v);
    l = __float2bfloat16(v - __bfloat162float(h));
}
__device__ __forceinline__ void ldmx4(uint32_t& r0, uint32_t& r1, uint32_t& r2, uint32_t& r3,
                                      uint32_t addr) {
    asm volatile("ldmatrix.sync.aligned.m8n8.x4.shared.b16 {%0,%1,%2,%3}, [%4];"
                 : "=r"(r0), "=r"(r1), "=r"(r2), "=r"(r3) : "r"(addr));
}
__device__ __forceinline__ void mma16816(float* d, const uint32_t* a, uint32_t b0, uint32_t b1) {
    asm volatile(
        "mma.sync.aligned.m16n8k16.row.col.f32.bf16.bf16.f32 "
        "{%0,%1,%2,%3},{%4,%5,%6,%7},{%8,%9},{%0,%1,%2,%3};"
        : "+f"(d[0]), "+f"(d[1]), "+f"(d[2]), "+f"(d[3])
        : "r"(a[0]), "r"(a[1]), "r"(a[2]), "r"(a[3]), "r"(b0), "r"(b1));
}
#define CP16(dst, src, sz) \
    asm volatile("cp.async.cg.shared.global [%0], [%1], 16, %2;" \
                 :: "r"(dst), "l"(src), "r"(sz))
#define CP_COMMIT() asm volatile("cp.async.commit_group;")
template<int N> __device__ __forceinline__ void cp_wait() {
    asm volatile("cp.async.wait_group %0;" :: "n"(N));
}

// ---------------- merged weight pre-conversion (one launch) ----------------
__global__ void __launch_bounds__(256)
cvt_all(const float* __restrict__ pw, const float* __restrict__ qw,
        const float* __restrict__ prw, const float* __restrict__ f1w,
        const float* __restrict__ f2w,
        __nv_bfloat16* __restrict__ hi, __nv_bfloat16* __restrict__ lo)
{
    const int n4 = NW_TOTAL / 4;
    for (int i = blockIdx.x * blockDim.x + threadIdx.x; i < n4; i += gridDim.x * blockDim.x) {
        const float* src;
        int local;
        if (i < OFF_QKV / 4)        { src = pw;  local = i; }
        else if (i < OFF_PROJ / 4)  { src = qw;  local = i - OFF_QKV / 4; }
        else if (i < OFF_FC1 / 4)   { src = prw; local = i - OFF_PROJ / 4; }
        else if (i < OFF_FC2 / 4)   { src = f1w; local = i - OFF_FC1 / 4; }
        else                        { src = f2w; local = i - OFF_FC2 / 4; }
        float4 f = reinterpret_cast<const float4*>(src)[local];
        __nv_bfloat16 h0, h1, h2, h3, l0, l1, l2, l3;
        split1(f.x, h0, l0); split1(f.y, h1, l1);
        split1(f.z, h2, l2); split1(f.w, h3, l3);
        uint2 H, L;
        H.x = pack_bf16(h0, h1); H.y = pack_bf16(h2, h3);
        L.x = pack_bf16(l0, l1); L.y = pack_bf16(l2, l3);
        reinterpret_cast<uint2*>(hi)[i] = H;
        reinterpret_cast<uint2*>(lo)[i] = L;
    }
}

// ---------------- HMMA GEMM (bf16x3, cp.async 2-stage) ----------------
// EPI: 0 bias->fp32, 1 bias+GELU->bf16 hi/lo, 2 bias+residual->fp32,
//      3 bias+pos_embed scatter (patch embed; res = pos_embed)
template<int BM, int BN, int EPI, int OCC>
__global__ void __launch_bounds__(BM*2, OCC)
hgemm(const __nv_bfloat16* __restrict__ Ah, const __nv_bfloat16* __restrict__ Al,
      const __nv_bfloat16* __restrict__ Wh, const __nv_bfloat16* __restrict__ Wl,
      const float* __restrict__ bias, const float* __restrict__ res,
      float* __restrict__ C, __nv_bfloat16* __restrict__ Ch, __nv_bfloat16* __restrict__ Cl,
      int Nrows, int K, int M)
{
    constexpr int BK = 32;
    constexpr int THREADS = BM * 2;
    constexpr int MW = BM / 32;              // m-warps; n-warps always 2
    constexpr int WN = BN / 2;               // per-warp n extent
    constexpr int NJ = WN / 8;               // 8-col accumulator groups per warp
    constexpr int NB2 = WN / 16;             // 16-row ldmatrix groups per warp
    constexpr int ASTB = 80;
    constexpr int ABYTES = BM * ASTB;
    constexpr int BBYTES = BN * ASTB;
    constexpr int STAGE = 2 * ABYTES + 2 * BBYTES;
    constexpr int O_AH = 0, O_AL = ABYTES, O_BH = 2 * ABYTES, O_BL = 2 * ABYTES + BBYTES;

    extern __shared__ char sm_[];
    const uint32_t sbase = smem_u32(sm_);

    const int tid  = threadIdx.x;
    const int lane = tid & 31;
    const int wid  = tid >> 5;
    const int wm   = wid % MW;
    const int wn   = wid / MW;
    const int row0 = blockIdx.y * BM;
    const int col0 = blockIdx.x * BN;

    int asz[2];
    uint32_t adst[2];
    const __nv_bfloat16 *ahs[2], *als[2];
#pragma unroll
    for (int i = 0; i < 2; i++) {
        int u = tid + i * THREADS;
        int r = u >> 2, q = u & 3;
        asz[i]  = (row0 + r < Nrows) ? 16 : 0;
        adst[i] = (uint32_t)(r * ASTB + q * 16);
        ahs[i]  = Ah + (size_t)(row0 + r) * K + q * 8;
        als[i]  = Al + (size_t)(row0 + r) * K + q * 8;
    }
    constexpr int BU = (BN * 4) / THREADS;
    uint32_t bdst[BU];
    const __nv_bfloat16 *bhs[BU], *bls[BU];
#pragma unroll
    for (int i = 0; i < BU; i++) {
        int u = tid + i * THREADS;
        int r = u >> 2, q = u & 3;
        bdst[i] = (uint32_t)(r * ASTB + q * 16);
        bhs[i]  = Wh + (size_t)(col0 + r) * K + q * 8;
        bls[i]  = Wl + (size_t)(col0 + r) * K + q * 8;
    }

    uint32_t aoff[2], boff[NB2];
#pragma unroll
    for (int mi = 0; mi < 2; mi++)
        aoff[mi] = (uint32_t)((wm * 32 + mi * 16 + (lane & 15)) * ASTB + (lane >> 4) * 16);
#pragma unroll
    for (int nj2 = 0; nj2 < NB2; nj2++)
        boff[nj2] = (uint32_t)((wn * WN + nj2 * 16 + (lane & 7) + ((lane >> 4) << 3)) * ASTB
                               + ((lane >> 3) & 1) * 16);

    float acc[2][NJ][4];
#pragma unroll
    for (int mi = 0; mi < 2; mi++)
#pragma unroll
        for (int nj = 0; nj < NJ; nj++)
#pragma unroll
            for (int v = 0; v < 4; v++) acc[mi][nj][v] = 0.f;

    const int KT = K / BK;

    auto load_stage = [&](int s, int k0) {
        const uint32_t sb = sbase + (uint32_t)(s * STAGE);
#pragma unroll
        for (int i = 0; i < 2; i++) {
            CP16(sb + O_AH + adst[i], ahs[i] + k0, asz[i]);
            CP16(sb + O_AL + adst[i], als[i] + k0, asz[i]);
        }
#pragma unroll
        for (int i = 0; i < BU; i++) {
            CP16(sb + O_BH + bdst[i], bhs[i] + k0, 16);
            CP16(sb + O_BL + bdst[i], bls[i] + k0, 16);
        }
    };

    load_stage(0, 0);
    CP_COMMIT();

    for (int kt = 0; kt < KT; kt++) {
        cp_wait<0>();
        __syncthreads();
        if (kt + 1 < KT) {
            load_stage((kt + 1) & 1, (kt + 1) * BK);
            CP_COMMIT();
        }

        const uint32_t sb = sbase + (uint32_t)((kt & 1) * STAGE);
#pragma unroll
        for (int k16 = 0; k16 < 2; k16++) {
            const uint32_t kb = (uint32_t)(k16 * 32);
            uint32_t ah[2][4], al[2][4], bh[NB2][4], bl[NB2][4];
#pragma unroll
            for (int mi = 0; mi < 2; mi++)
                ldmx4(ah[mi][0], ah[mi][1], ah[mi][2], ah[mi][3], sb + O_AH + aoff[mi] + kb);
#pragma unroll
            for (int nj2 = 0; nj2 < NB2; nj2++)
                ldmx4(bh[nj2][0], bh[nj2][1], bh[nj2][2], bh[nj2][3], sb + O_BH + boff[nj2] + kb);
            // hi*hi
#pragma unroll
            for (int mi = 0; mi < 2; mi++)
#pragma unroll
                for (int nj = 0; nj < NJ; nj++)
                    mma16816(acc[mi][nj], ah[mi],
                             bh[nj >> 1][(nj & 1) * 2], bh[nj >> 1][(nj & 1) * 2 + 1]);
            // hi*lo
#pragma unroll
            for (int nj2 = 0; nj2 < NB2; nj2++)
                ldmx4(bl[nj2][0], bl[nj2][1], bl[nj2][2], bl[nj2][3], sb + O_BL + boff[nj2] + kb);
#pragma unroll
            for (int mi = 0; mi < 2; mi++)
#pragma unroll
                for (int nj = 0; nj < NJ; nj++)
                    mma16816(acc[mi][nj], ah[mi],
                             bl[nj >> 1][(nj & 1) * 2], bl[nj >> 1][(nj & 1) * 2 + 1]);
            // lo*hi
#pragma unroll
            for (int mi = 0; mi < 2; mi++)
                ldmx4(al[mi][0], al[mi][1], al[mi][2], al[mi][3], sb + O_AL + aoff[mi] + kb);
#pragma unroll
            for (int mi = 0; mi < 2; mi++)
#pragma unroll
                for (int nj = 0; nj < NJ; nj++)
                    mma16816(acc[mi][nj], al[mi],
                             bh[nj >> 1][(nj & 1) * 2], bh[nj >> 1][(nj & 1) * 2 + 1]);
        }
    }

    // ---- epilogue ----
    const int g  = lane >> 2;
    const int tg = lane & 3;
#pragma unroll
    for (int mi = 0; mi < 2; mi++) {
#pragma unroll
        for (int half = 0; half < 2; half++) {
            const int r = row0 + wm * 32 + mi * 16 + g + half * 8;
            if (r >= Nrows) continue;
#pragma unroll
            for (int nj = 0; nj < NJ; nj++) {
                const int c = col0 + wn * WN + nj * 8 + tg * 2;
                float v0 = acc[mi][nj][half * 2 + 0] + bias[c];
                float v1 = acc[mi][nj][half * 2 + 1] + bias[c + 1];
                if (EPI == 1) {
                    v0 = 0.5f * v0 * (1.0f + erff(v0 * 0.7071067811865475f));
                    v1 = 0.5f * v1 * (1.0f + erff(v1 * 0.7071067811865475f));
                    __nv_bfloat16 h0, l0, h1, l1;
                    split1(v0, h0, l0); split1(v1, h1, l1);
                    *reinterpret_cast<uint32_t*>(Ch + (size_t)r * M + c) = pack_bf16(h0, h1);
                    *reinterpret_cast<uint32_t*>(Cl + (size_t)r * M + c) = pack_bf16(l0, l1);
                } else if (EPI == 3) {
                    const int bb   = r / NPATCH;
                    const int orow = r + bb + 1;
                    const int prow = r - bb * NPATCH + 1;
                    v0 += res[(size_t)prow * M + c];
                    v1 += res[(size_t)prow * M + c + 1];
                    C[(size_t)orow * M + c]     = v0;
                    C[(size_t)orow * M + c + 1] = v1;
                } else {
                    if (EPI == 2) {
                        v0 += res[(size_t)r * M + c];
                        v1 += res[(size_t)r * M + c + 1];
                    }
                    C[(size_t)r * M + c]     = v0;
                    C[(size_t)r * M + c + 1] = v1;
                }
            }
        }
    }
}

// ---------------- LayerNorm (warp-shuffle) -> bf16 hi/lo ----------------
__global__ void __launch_bounds__(256)
ln_kernel(const float* __restrict__ x, const float* __restrict__ s,
          const float* __restrict__ b, __nv_bfloat16* __restrict__ yh,
          __nv_bfloat16* __restrict__ yl)
{
    const int row  = blockIdx.x;
    const int tid  = threadIdx.x;
    const int warp = tid >> 5;
    const int lane = tid & 31;
    const float* xr = x + (size_t)row * DIM;

    float v0 = xr[tid];
    float v1 = xr[tid + 256];
    float v2 = xr[tid + 512];

    float sum = v0 + v1 + v2;
    float sq  = v0 * v0 + v1 * v1 + v2 * v2;
#pragma unroll
    for (int o = 16; o; o >>= 1) {
        sum += __shfl_xor_sync(0xffffffffu, sum, o);
        sq  += __shfl_xor_sync(0xffffffffu, sq, o);
    }
    __shared__ float ws[8], wq[8];
    if (lane == 0) { ws[warp] = sum; wq[warp] = sq; }
    __syncthreads();
    if (tid < 32) {
        float s2 = (lane < 8) ? ws[lane] : 0.f;
        float q2 = (lane < 8) ? wq[lane] : 0.f;
#pragma unroll
        for (int o = 4; o; o >>= 1) {
            s2 += __shfl_xor_sync(0xffffffffu, s2, o);
            q2 += __shfl_xor_sync(0xffffffffu, q2, o);
        }
        if (lane == 0) { ws[0] = s2; wq[0] = q2; }
    }
    __syncthreads();
    const float mean = ws[0] * (1.0f / DIM);
    const float var  = wq[0] * (1.0f / DIM) - mean * mean;
    const float inv  = rsqrtf(var + 1e-5f);

    __nv_bfloat16 h, l;
    size_t o = (size_t)row * DIM;
    float y0 = (v0 - mean) * inv * s[tid]       + b[tid];
    float y1 = (v1 - mean) * inv * s[tid + 256] + b[tid + 256];
    float y2 = (v2 - mean) * inv * s[tid + 512] + b[tid + 512];
    split1(y0, h, l); yh[o + tid]       = h; yl[o + tid]       = l;
    split1(y1, h, l); yh[o + tid + 256] = h; yl[o + tid + 256] = l;
    split1(y2, h, l); yh[o + tid + 512] = h; yl[o + tid + 512] = l;
}

// ---------------- Attention -> bf16 hi/lo (4 warps, float4 scores, unrolled V) ----------------
__global__ void __launch_bounds__(128)
attn_kernel(const float* __restrict__ qkv, const int* __restrict__ routes,
            __nv_bfloat16* __restrict__ outh, __nv_bfloat16* __restrict__ outl)
{
    __shared__ float sc[4][200];
    __shared__ int   sidx[4][200];
    __shared__ float qs[4][64];

    const int bh   = blockIdx.x;
    const int b    = bh / NHEAD;
    const int h    = bh % NHEAD;
    const int warp = threadIdx.x >> 5;
    const int lane = threadIdx.x & 31;
    const int s    = blockIdx.y * 4 + warp;
    if (s >= SEQ) return;

    const float* base = qkv + (size_t)b * SEQ * (3 * DIM);
    const float* qp = base + (size_t)s * (3 * DIM) + h * HDIM;
    qs[warp][lane]      = qp[lane];
    qs[warp][lane + 32] = qp[lane + 32];
    __syncwarp();

    const int nk = (s == 0) ? SEQ : TOPK;

    const float4* qs4 = reinterpret_cast<const float4*>(&qs[warp][0]);
    for (int j = lane; j < nk; j += 32) {
        int kidx = (s == 0) ? j : (routes[(s - 1) * TOPK + j] + 1);
        const float4* kp4 = reinterpret_cast<const float4*>(
            base + (size_t)kidx * (3 * DIM) + DIM + h * HDIM);
        float acc = 0.f;
#pragma unroll
        for (int d4 = 0; d4 < 16; d4++) {
            float4 kv = kp4[d4];
            float4 qv = qs4[d4];
            acc = fmaf(qv.x, kv.x, acc);
            acc = fmaf(qv.y, kv.y, acc);
            acc = fmaf(qv.z, kv.z, acc);
            acc = fmaf(qv.w, kv.w, acc);
        }
        sc[warp][j]   = acc * ATT_SCALE;
        sidx[warp][j] = kidx;
    }
    __syncwarp();

    float m = -1e30f;
    for (int j = lane; j < nk; j += 32) m = fmaxf(m, sc[warp][j]);
#pragma unroll
    for (int o = 16; o; o >>= 1) m = fmaxf(m, __shfl_xor_sync(0xffffffffu, m, o));

    float sum = 0.f;
    for (int j = lane; j < nk; j += 32) {
        float e = expf(sc[warp][j] - m);
        sc[warp][j] = e;
        sum += e;
    }
#pragma unroll
    for (int o = 16; o; o >>= 1) sum += __shfl_xor_sync(0xffffffffu, sum, o);
    __syncwarp();
    const float inv = 1.f / sum;

    float o0 = 0.f, o1 = 0.f;
#pragma unroll 4
    for (int j = 0; j < nk; j++) {
        float p = sc[warp][j];
        const float2* vp2 = reinterpret_cast<const float2*>(
            base + (size_t)sidx[warp][j] * (3 * DIM) + 2 * DIM + h * HDIM);
        float2 vv = vp2[lane];
        o0 = fmaf(p, vv.x, o0);
        o1 = fmaf(p, vv.y, o1);
    }
    size_t ob = ((size_t)(b * SEQ + s)) * DIM + h * HDIM;
    __nv_bfloat16 h0, l0, h1, l1;
    split1(o0 * inv, h0, l0);
    split1(o1 * inv, h1, l1);
    *reinterpret_cast<uint32_t*>(outh + ob + 2 * lane) = pack_bf16(h0, h1);
    *reinterpret_cast<uint32_t*>(outl + ob + 2 * lane) = pack_bf16(l0, l1);
}

// ---------------- Patchify -> bf16 hi/lo, plus cls rows -> h ----------------
__global__ void patchify_kernel(const float* __restrict__ x,
                                __nv_bfloat16* __restrict__ xph, __nv_bfloat16* __restrict__ xpl,
                                const float* __restrict__ cls, const float* __restrict__ pos,
                                float* __restrict__ hout)
{
    int idx = blockIdx.x * blockDim.x + threadIdx.x;
    const int total = NROWS_P * DIM;
    if (idx < total) {
        int e  = idx % DIM;
        int bp = idx / DIM;
        int p  = bp % NPATCH;
        int b  = bp / NPATCH;
        int c  = e / (PATCH * PATCH);
        int r  = e % (PATCH * PATCH);
        int py = r / PATCH, px = r % PATCH;
        int gy = p / GRID,  gx = p % GRID;
        float v = x[(((size_t)b * CHN + c) * IMG + gy * PATCH + py) * IMG + gx * PATCH + px];
        __nv_bfloat16 h, l;
        split1(v, h, l);
        xph[idx] = h;
        xpl[idx] = l;
    } else {
        int k = idx - total;          // cls element
        if (k >= BATCH * DIM) return;
        int d = k % DIM;
        int b = k / DIM;
        hout[(size_t)(b * SEQ) * DIM + d] = cls[d] + pos[d];
    }
}

// ---------------- host launcher ----------------
extern "C" void kernel_launch(void* const* d_in, const int* in_sizes, int n_in,
                              void* d_out, int out_size)
{
    const float* x        = (const float*)d_in[0];
    const float* patch_w  = (const float*)d_in[1];
    const float* patch_b  = (const float*)d_in[2];
    const float* cls_tok  = (const float*)d_in[3];
    const float* pos_emb  = (const float*)d_in[4];
    const float* qkv_w    = (const float*)d_in[5];
    const float* qkv_b    = (const float*)d_in[6];
    const float* proj_w   = (const float*)d_in[7];
    const float* proj_b   = (const float*)d_in[8];
    const float* ln1_s    = (const float*)d_in[9];
    const float* ln1_b    = (const float*)d_in[10];
    const float* ln2_s    = (const float*)d_in[11];
    const float* ln2_b    = (const float*)d_in[12];
    const float* fc1_w    = (const float*)d_in[13];
    const float* fc1_b    = (const float*)d_in[14];
    const float* fc2_w    = (const float*)d_in[15];
    const float* fc2_b    = (const float*)d_in[16];
    const int*   routes   = (const int*)d_in[17];

    float *hbuf, *qkv;
    __nv_bfloat16 *xnh, *xnl, *atth, *attl, *mlph, *mlpl, *wh, *wl;
    cudaGetSymbolAddress((void**)&hbuf, g_h);
    cudaGetSymbolAddress((void**)&qkv,  g_qkv);
    cudaGetSymbolAddress((void**)&xnh,  g_xnh);
    cudaGetSymbolAddress((void**)&xnl,  g_xnl);
    cudaGetSymbolAddress((void**)&atth, g_atth);
    cudaGetSymbolAddress((void**)&attl, g_attl);
    cudaGetSymbolAddress((void**)&mlph, g_mlph);
    cudaGetSymbolAddress((void**)&mlpl, g_mlpl);
    cudaGetSymbolAddress((void**)&wh,   g_wh);
    cudaGetSymbolAddress((void**)&wl,   g_wl);

    // smem per config
    const int SMEM_64_128  = 2 * (2 * 64 * 80 + 2 * 128 * 80);   // 61440, occ 3
    const int SMEM_64_64   = 2 * (2 * 64 * 80 + 2 * 64 * 80);    // 40960, occ 4
    cudaFuncSetAttribute(hgemm<64, 128, 0, 3>,  cudaFuncAttributeMaxDynamicSharedMemorySize, SMEM_64_128);
    cudaFuncSetAttribute(hgemm<64, 128, 3, 3>,  cudaFuncAttributeMaxDynamicSharedMemorySize, SMEM_64_128);
    cudaFuncSetAttribute(hgemm<64, 64, 1, 4>,   cudaFuncAttributeMaxDynamicSharedMemorySize, SMEM_64_64);
    cudaFuncSetAttribute(hgemm<64, 64, 2, 4>,   cudaFuncAttributeMaxDynamicSharedMemorySize, SMEM_64_64);

    // one-time weight split (single merged launch)
    cvt_all<<<(NW_TOTAL / 4 + 255) / 256, 256>>>(patch_w, qkv_w, proj_w, fc1_w, fc2_w, wh, wl);

    const int rt64  = (NROWS + 63) / 64;     // 25
    const int rt64p = (NROWS_P + 63) / 64;   // 25

    // patch embed: patchify(+cls) -> GEMM (EPI=3: +pos scatter to h)
    {
        int tot = NROWS_P * DIM + BATCH * DIM;
        patchify_kernel<<<(tot + 255) / 256, 256>>>(x, mlph, mlpl, cls_tok, pos_emb, hbuf);
        hgemm<64, 128, 3, 3><<<dim3(DIM / 128, rt64p), 128, SMEM_64_128>>>(
            mlph, mlpl, wh + OFF_PATCH, wl + OFF_PATCH, patch_b, pos_emb,
            hbuf, nullptr, nullptr, NROWS_P, DIM, DIM);
    }

    for (int l = 0; l < NLAYER; l++) {
        const size_t oq  = OFF_QKV  + (size_t)l * 3 * DIM * DIM;
        const size_t op  = OFF_PROJ + (size_t)l * DIM * DIM;
        const size_t of1 = OFF_FC1  + (size_t)l * MLPDIM * DIM;
        const size_t of2 = OFF_FC2  + (size_t)l * DIM * MLPDIM;
        const float* qb  = qkv_b  + (size_t)l * 3 * DIM;
        const float* pb  = proj_b + (size_t)l * DIM;
        const float* f1b = fc1_b  + (size_t)l * MLPDIM;
        const float* f2b = fc2_b  + (size_t)l * DIM;

        ln_kernel<<<NROWS, 256>>>(hbuf, ln1_s + (size_t)l * DIM, ln1_b + (size_t)l * DIM,
                                  xnh, xnl);
        // QKV: BM=64/BN=128, occ 3 -> 18x25 = 450 blocks (R13 champion config)
        hgemm<64, 128, 0, 3><<<dim3(3 * DIM / 128, rt64), 128, SMEM_64_128>>>(
            xnh, xnl, wh + oq, wl + oq, qb, nullptr,
            qkv, nullptr, nullptr, NROWS, DIM, 3 * DIM);
        attn_kernel<<<dim3(BATCH * NHEAD, (SEQ + 3) / 4), 128>>>(qkv, routes, atth, attl);
        hgemm<64, 64, 2, 4><<<dim3(DIM / 64, rt64), 128, SMEM_64_64>>>(
            atth, attl, wh + op, wl + op, pb, hbuf,
            hbuf, nullptr, nullptr, NROWS, DIM, DIM);
        ln_kernel<<<NROWS, 256>>>(hbuf, ln2_s + (size_t)l * DIM, ln2_b + (size_t)l * DIM,
                                  xnh, xnl);
        hgemm<64, 64, 1, 4><<<dim3(MLPDIM / 64, rt64), 128, SMEM_64_64>>>(
            xnh, xnl, wh + of1, wl + of1, f1b, nullptr,
            nullptr, mlph, mlpl, NROWS, DIM, MLPDIM);
        float* outp = (l == NLAYER - 1) ? (float*)d_out : hbuf;
        hgemm<64, 64, 2, 4><<<dim3(DIM / 64, rt64), 128, SMEM_64_64>>>(
            mlph, mlpl, wh + of2, wl + of2, f2b, hbuf,
            outp, nullptr, nullptr, NROWS, MLPDIM, DIM);
    }
}

// round 17
// speedup vs baseline: 1.0131x; 1.0131x over previous
#include <cuda_runtime.h>
#include <cuda_bf16.h>
#include <math.h>
#include <stdint.h>

// ---------------- problem constants ----------------
#define BATCH 8
#define CHN 3
#define IMG 224
#define PATCH 16
#define GRID 14
#define NPATCH 196
#define SEQ 197
#define DIM 768
#define NHEAD 12
#define HDIM 64
#define NLAYER 12
#define TOPK 32
#define MLPDIM 3072
#define ATT_SCALE 0.125f

#define NROWS (BATCH*SEQ)           // 1576
#define NROWS_P (BATCH*NPATCH)      // 1568

#define NW_PATCH (DIM*DIM)
#define NW_QKV   (NLAYER*3*DIM*DIM)
#define NW_PROJ  (NLAYER*DIM*DIM)
#define NW_FC1   (NLAYER*MLPDIM*DIM)
#define NW_FC2   (NLAYER*DIM*MLPDIM)
#define OFF_PATCH 0
#define OFF_QKV   (OFF_PATCH + NW_PATCH)
#define OFF_PROJ  (OFF_QKV + NW_QKV)
#define OFF_FC1   (OFF_PROJ + NW_PROJ)
#define OFF_FC2   (OFF_FC1 + NW_FC1)
#define NW_TOTAL  (OFF_FC2 + NW_FC2)

// ---------------- scratch ----------------
__device__ float g_h  [BATCH*SEQ*DIM];
__device__ float g_qkv[BATCH*SEQ*3*DIM];
__device__ __nv_bfloat16 g_xnh [BATCH*SEQ*DIM];
__device__ __nv_bfloat16 g_xnl [BATCH*SEQ*DIM];
__device__ __nv_bfloat16 g_atth[BATCH*SEQ*DIM];
__device__ __nv_bfloat16 g_attl[BATCH*SEQ*DIM];
__device__ __nv_bfloat16 g_mlph[BATCH*SEQ*MLPDIM];
__device__ __nv_bfloat16 g_mlpl[BATCH*SEQ*MLPDIM];
__device__ __nv_bfloat16 g_wh[NW_TOTAL];
__device__ __nv_bfloat16 g_wl[NW_TOTAL];

// ---------------- helpers ----------------
__device__ __forceinline__ uint32_t smem_u32(const void* p) {
    uint32_t a;
    asm("{ .reg .u64 t; cvta.to.shared.u64 t, %1; cvt.u32.u64 %0, t; }" : "=r"(a) : "l"(p));
    return a;
}
__device__ __forceinline__ uint32_t pack_bf16(__nv_bfloat16 a, __nv_bfloat16 b) {
    return (uint32_t)__bfloat16_as_ushort(a) | ((uint32_t)__bfloat16_as_ushort(b) << 16);
}
__device__ __forceinline__ void split1(float v, __nv_bfloat16& h, __nv_bfloat16& l) {
    h = __float2bfloat16(v);
    l = __float2bfloat16(v - __bfloat162float(h));
}
__device__ __forceinline__ void ldmx4(uint32_t& r0, uint32_t& r1, uint32_t& r2, uint32_t& r3,
                                      uint32_t addr) {
    asm volatile("ldmatrix.sync.aligned.m8n8.x4.shared.b16 {%0,%1,%2,%3}, [%4];"
                 : "=r"(r0), "=r"(r1), "=r"(r2), "=r"(r3) : "r"(addr));
}
__device__ __forceinline__ void mma16816(float* d, const uint32_t* a, uint32_t b0, uint32_t b1) {
    asm volatile(
        "mma.sync.aligned.m16n8k16.row.col.f32.bf16.bf16.f32 "
        "{%0,%1,%2,%3},{%4,%5,%6,%7},{%8,%9},{%0,%1,%2,%3};"
        : "+f"(d[0]), "+f"(d[1]), "+f"(d[2]), "+f"(d[3])
        : "r"(a[0]), "r"(a[1]), "r"(a[2]), "r"(a[3]), "r"(b0), "r"(b1));
}
#define CP16(dst, src, sz) \
    asm volatile("cp.async.cg.shared.global [%0], [%1], 16, %2;" \
                 :: "r"(dst), "l"(src), "r"(sz))
#define CP_COMMIT() asm volatile("cp.async.commit_group;")
template<int N> __device__ __forceinline__ void cp_wait() {
    asm volatile("cp.async.wait_group %0;" :: "n"(N));
}

// ---------------- merged weight pre-conversion (one launch) ----------------
__global__ void __launch_bounds__(256)
cvt_all(const float* __restrict__ pw, const float* __restrict__ qw,
        const float* __restrict__ prw, const float* __restrict__ f1w,
        const float* __restrict__ f2w,
        __nv_bfloat16* __restrict__ hi, __nv_bfloat16* __restrict__ lo)
{
    const int n4 = NW_TOTAL / 4;
    for (int i = blockIdx.x * blockDim.x + threadIdx.x; i < n4; i += gridDim.x * blockDim.x) {
        const float* src;
        int local;
        if (i < OFF_QKV / 4)        { src = pw;  local = i; }
        else if (i < OFF_PROJ / 4)  { src = qw;  local = i - OFF_QKV / 4; }
        else if (i < OFF_FC1 / 4)   { src = prw; local = i - OFF_PROJ / 4; }
        else if (i < OFF_FC2 / 4)   { src = f1w; local = i - OFF_FC1 / 4; }
        else                        { src = f2w; local = i - OFF_FC2 / 4; }
        float4 f = reinterpret_cast<const float4*>(src)[local];
        __nv_bfloat16 h0, h1, h2, h3, l0, l1, l2, l3;
        split1(f.x, h0, l0); split1(f.y, h1, l1);
        split1(f.z, h2, l2); split1(f.w, h3, l3);
        uint2 H, L;
        H.x = pack_bf16(h0, h1); H.y = pack_bf16(h2, h3);
        L.x = pack_bf16(l0, l1); L.y = pack_bf16(l2, l3);
        reinterpret_cast<uint2*>(hi)[i] = H;
        reinterpret_cast<uint2*>(lo)[i] = L;
    }
}

// ---------------- HMMA GEMM (bf16x3, cp.async 2-stage) ----------------
// EPI: 0 bias->fp32, 1 bias+GELU->bf16 hi/lo, 2 bias+residual->fp32,
//      3 bias+pos_embed scatter (patch embed; res = pos_embed)
template<int BM, int BN, int EPI, int OCC>
__global__ void __launch_bounds__(BM*2, OCC)
hgemm(const __nv_bfloat16* __restrict__ Ah, const __nv_bfloat16* __restrict__ Al,
      const __nv_bfloat16* __restrict__ Wh, const __nv_bfloat16* __restrict__ Wl,
      const float* __restrict__ bias, const float* __restrict__ res,
      float* __restrict__ C, __nv_bfloat16* __restrict__ Ch, __nv_bfloat16* __restrict__ Cl,
      int Nrows, int K, int M)
{
    constexpr int BK = 32;
    constexpr int THREADS = BM * 2;
    constexpr int MW = BM / 32;              // m-warps; n-warps always 2
    constexpr int WN = BN / 2;               // per-warp n extent
    constexpr int NJ = WN / 8;               // 8-col accumulator groups per warp
    constexpr int NB2 = WN / 16;             // 16-row ldmatrix groups per warp
    constexpr int ASTB = 80;
    constexpr int ABYTES = BM * ASTB;
    constexpr int BBYTES = BN * ASTB;
    constexpr int STAGE = 2 * ABYTES + 2 * BBYTES;
    constexpr int O_AH = 0, O_AL = ABYTES, O_BH = 2 * ABYTES, O_BL = 2 * ABYTES + BBYTES;

    extern __shared__ char sm_[];
    const uint32_t sbase = smem_u32(sm_);

    const int tid  = threadIdx.x;
    const int lane = tid & 31;
    const int wid  = tid >> 5;
    const int wm   = wid % MW;
    const int wn   = wid / MW;
    const int row0 = blockIdx.y * BM;
    const int col0 = blockIdx.x * BN;

    int asz[2];
    uint32_t adst[2];
    const __nv_bfloat16 *ahs[2], *als[2];
#pragma unroll
    for (int i = 0; i < 2; i++) {
        int u = tid + i * THREADS;
        int r = u >> 2, q = u & 3;
        asz[i]  = (row0 + r < Nrows) ? 16 : 0;
        adst[i] = (uint32_t)(r * ASTB + q * 16);
        ahs[i]  = Ah + (size_t)(row0 + r) * K + q * 8;
        als[i]  = Al + (size_t)(row0 + r) * K + q * 8;
    }
    constexpr int BU = (BN * 4) / THREADS;
    uint32_t bdst[BU];
    const __nv_bfloat16 *bhs[BU], *bls[BU];
#pragma unroll
    for (int i = 0; i < BU; i++) {
        int u = tid + i * THREADS;
        int r = u >> 2, q = u & 3;
        bdst[i] = (uint32_t)(r * ASTB + q * 16);
        bhs[i]  = Wh + (size_t)(col0 + r) * K + q * 8;
        bls[i]  = Wl + (size_t)(col0 + r) * K + q * 8;
    }

    uint32_t aoff[2], boff[NB2];
#pragma unroll
    for (int mi = 0; mi < 2; mi++)
        aoff[mi] = (uint32_t)((wm * 32 + mi * 16 + (lane & 15)) * ASTB + (lane >> 4) * 16);
#pragma unroll
    for (int nj2 = 0; nj2 < NB2; nj2++)
        boff[nj2] = (uint32_t)((wn * WN + nj2 * 16 + (lane & 7) + ((lane >> 4) << 3)) * ASTB
                               + ((lane >> 3) & 1) * 16);

    float acc[2][NJ][4];
#pragma unroll
    for (int mi = 0; mi < 2; mi++)
#pragma unroll
        for (int nj = 0; nj < NJ; nj++)
#pragma unroll
            for (int v = 0; v < 4; v++) acc[mi][nj][v] = 0.f;

    const int KT = K / BK;

    auto load_stage = [&](int s, int k0) {
        const uint32_t sb = sbase + (uint32_t)(s * STAGE);
#pragma unroll
        for (int i = 0; i < 2; i++) {
            CP16(sb + O_AH + adst[i], ahs[i] + k0, asz[i]);
            CP16(sb + O_AL + adst[i], als[i] + k0, asz[i]);
        }
#pragma unroll
        for (int i = 0; i < BU; i++) {
            CP16(sb + O_BH + bdst[i], bhs[i] + k0, 16);
            CP16(sb + O_BL + bdst[i], bls[i] + k0, 16);
        }
    };

    load_stage(0, 0);
    CP_COMMIT();

    for (int kt = 0; kt < KT; kt++) {
        cp_wait<0>();
        __syncthreads();
        if (kt + 1 < KT) {
            load_stage((kt + 1) & 1, (kt + 1) * BK);
            CP_COMMIT();
        }

        const uint32_t sb = sbase + (uint32_t)((kt & 1) * STAGE);
#pragma unroll
        for (int k16 = 0; k16 < 2; k16++) {
            const uint32_t kb = (uint32_t)(k16 * 32);
            uint32_t ah[2][4], al[2][4], bh[NB2][4], bl[NB2][4];
#pragma unroll
            for (int mi = 0; mi < 2; mi++)
                ldmx4(ah[mi][0], ah[mi][1], ah[mi][2], ah[mi][3], sb + O_AH + aoff[mi] + kb);
#pragma unroll
            for (int nj2 = 0; nj2 < NB2; nj2++)
                ldmx4(bh[nj2][0], bh[nj2][1], bh[nj2][2], bh[nj2][3], sb + O_BH + boff[nj2] + kb);
            // hi*hi
#pragma unroll
            for (int mi = 0; mi < 2; mi++)
#pragma unroll
                for (int nj = 0; nj < NJ; nj++)
                    mma16816(acc[mi][nj], ah[mi],
                             bh[nj >> 1][(nj & 1) * 2], bh[nj >> 1][(nj & 1) * 2 + 1]);
            // hi*lo
#pragma unroll
            for (int nj2 = 0; nj2 < NB2; nj2++)
                ldmx4(bl[nj2][0], bl[nj2][1], bl[nj2][2], bl[nj2][3], sb + O_BL + boff[nj2] + kb);
#pragma unroll
            for (int mi = 0; mi < 2; mi++)
#pragma unroll
                for (int nj = 0; nj < NJ; nj++)
                    mma16816(acc[mi][nj], ah[mi],
                             bl[nj >> 1][(nj & 1) * 2], bl[nj >> 1][(nj & 1) * 2 + 1]);
            // lo*hi
#pragma unroll
            for (int mi = 0; mi < 2; mi++)
                ldmx4(al[mi][0], al[mi][1], al[mi][2], al[mi][3], sb + O_AL + aoff[mi] + kb);
#pragma unroll
            for (int mi = 0; mi < 2; mi++)
#pragma unroll
                for (int nj = 0; nj < NJ; nj++)
                    mma16816(acc[mi][nj], al[mi],
                             bh[nj >> 1][(nj & 1) * 2], bh[nj >> 1][(nj & 1) * 2 + 1]);
        }
    }

    // ---- epilogue ----
    const int g  = lane >> 2;
    const int tg = lane & 3;
#pragma unroll
    for (int mi = 0; mi < 2; mi++) {
#pragma unroll
        for (int half = 0; half < 2; half++) {
            const int r = row0 + wm * 32 + mi * 16 + g + half * 8;
            if (r >= Nrows) continue;
#pragma unroll
            for (int nj = 0; nj < NJ; nj++) {
                const int c = col0 + wn * WN + nj * 8 + tg * 2;
                float v0 = acc[mi][nj][half * 2 + 0] + bias[c];
                float v1 = acc[mi][nj][half * 2 + 1] + bias[c + 1];
                if (EPI == 1) {
                    v0 = 0.5f * v0 * (1.0f + erff(v0 * 0.7071067811865475f));
                    v1 = 0.5f * v1 * (1.0f + erff(v1 * 0.7071067811865475f));
                    __nv_bfloat16 h0, l0, h1, l1;
                    split1(v0, h0, l0); split1(v1, h1, l1);
                    *reinterpret_cast<uint32_t*>(Ch + (size_t)r * M + c) = pack_bf16(h0, h1);
                    *reinterpret_cast<uint32_t*>(Cl + (size_t)r * M + c) = pack_bf16(l0, l1);
                } else if (EPI == 3) {
                    const int bb   = r / NPATCH;
                    const int orow = r + bb + 1;
                    const int prow = r - bb * NPATCH + 1;
                    v0 += res[(size_t)prow * M + c];
                    v1 += res[(size_t)prow * M + c + 1];
                    C[(size_t)orow * M + c]     = v0;
                    C[(size_t)orow * M + c + 1] = v1;
                } else {
                    if (EPI == 2) {
                        v0 += res[(size_t)r * M + c];
                        v1 += res[(size_t)r * M + c + 1];
                    }
                    C[(size_t)r * M + c]     = v0;
                    C[(size_t)r * M + c + 1] = v1;
                }
            }
        }
    }
}

// ---------------- LayerNorm (warp-shuffle) -> bf16 hi/lo ----------------
__global__ void __launch_bounds__(256)
ln_kernel(const float* __restrict__ x, const float* __restrict__ s,
          const float* __restrict__ b, __nv_bfloat16* __restrict__ yh,
          __nv_bfloat16* __restrict__ yl)
{
    const int row  = blockIdx.x;
    const int tid  = threadIdx.x;
    const int warp = tid >> 5;
    const int lane = tid & 31;
    const float* xr = x + (size_t)row * DIM;

    float v0 = xr[tid];
    float v1 = xr[tid + 256];
    float v2 = xr[tid + 512];

    float sum = v0 + v1 + v2;
    float sq  = v0 * v0 + v1 * v1 + v2 * v2;
#pragma unroll
    for (int o = 16; o; o >>= 1) {
        sum += __shfl_xor_sync(0xffffffffu, sum, o);
        sq  += __shfl_xor_sync(0xffffffffu, sq, o);
    }
    __shared__ float ws[8], wq[8];
    if (lane == 0) { ws[warp] = sum; wq[warp] = sq; }
    __syncthreads();
    if (tid < 32) {
        float s2 = (lane < 8) ? ws[lane] : 0.f;
        float q2 = (lane < 8) ? wq[lane] : 0.f;
#pragma unroll
        for (int o = 4; o; o >>= 1) {
            s2 += __shfl_xor_sync(0xffffffffu, s2, o);
            q2 += __shfl_xor_sync(0xffffffffu, q2, o);
        }
        if (lane == 0) { ws[0] = s2; wq[0] = q2; }
    }
    __syncthreads();
    const float mean = ws[0] * (1.0f / DIM);
    const float var  = wq[0] * (1.0f / DIM) - mean * mean;
    const float inv  = rsqrtf(var + 1e-5f);

    __nv_bfloat16 h, l;
    size_t o = (size_t)row * DIM;
    float y0 = (v0 - mean) * inv * s[tid]       + b[tid];
    float y1 = (v1 - mean) * inv * s[tid + 256] + b[tid + 256];
    float y2 = (v2 - mean) * inv * s[tid + 512] + b[tid + 512];
    split1(y0, h, l); yh[o + tid]       = h; yl[o + tid]       = l;
    split1(y1, h, l); yh[o + tid + 256] = h; yl[o + tid + 256] = l;
    split1(y2, h, l); yh[o + tid + 512] = h; yl[o + tid + 512] = l;
}

// ---------------- Attention -> bf16 hi/lo (float4 scores, float2 V) ----------------
__global__ void __launch_bounds__(128)
attn_kernel(const float* __restrict__ qkv, const int* __restrict__ routes,
            __nv_bfloat16* __restrict__ outh, __nv_bfloat16* __restrict__ outl)
{
    __shared__ float sc[4][200];
    __shared__ int   sidx[4][200];
    __shared__ float qs[4][64];

    const int bh   = blockIdx.x;
    const int b    = bh / NHEAD;
    const int h    = bh % NHEAD;
    const int warp = threadIdx.x >> 5;
    const int lane = threadIdx.x & 31;
    const int s    = blockIdx.y * 4 + warp;
    if (s >= SEQ) return;

    const float* base = qkv + (size_t)b * SEQ * (3 * DIM);
    const float* qp = base + (size_t)s * (3 * DIM) + h * HDIM;
    qs[warp][lane]      = qp[lane];
    qs[warp][lane + 32] = qp[lane + 32];
    __syncwarp();

    const int nk = (s == 0) ? SEQ : TOPK;

    const float4* qs4 = reinterpret_cast<const float4*>(&qs[warp][0]);
    for (int j = lane; j < nk; j += 32) {
        int kidx = (s == 0) ? j : (routes[(s - 1) * TOPK + j] + 1);
        const float4* kp4 = reinterpret_cast<const float4*>(
            base + (size_t)kidx * (3 * DIM) + DIM + h * HDIM);
        float acc = 0.f;
#pragma unroll
        for (int d4 = 0; d4 < 16; d4++) {
            float4 kv = kp4[d4];
            float4 qv = qs4[d4];
            acc = fmaf(qv.x, kv.x, acc);
            acc = fmaf(qv.y, kv.y, acc);
            acc = fmaf(qv.z, kv.z, acc);
            acc = fmaf(qv.w, kv.w, acc);
        }
        sc[warp][j]   = acc * ATT_SCALE;
        sidx[warp][j] = kidx;
    }
    __syncwarp();

    float m = -1e30f;
    for (int j = lane; j < nk; j += 32) m = fmaxf(m, sc[warp][j]);
#pragma unroll
    for (int o = 16; o; o >>= 1) m = fmaxf(m, __shfl_xor_sync(0xffffffffu, m, o));

    float sum = 0.f;
    for (int j = lane; j < nk; j += 32) {
        float e = expf(sc[warp][j] - m);
        sc[warp][j] = e;
        sum += e;
    }
#pragma unroll
    for (int o = 16; o; o >>= 1) sum += __shfl_xor_sync(0xffffffffu, sum, o);
    __syncwarp();
    const float inv = 1.f / sum;

    float o0 = 0.f, o1 = 0.f;
    for (int j = 0; j < nk; j++) {
        float p = sc[warp][j];
        const float2* vp2 = reinterpret_cast<const float2*>(
            base + (size_t)sidx[warp][j] * (3 * DIM) + 2 * DIM + h * HDIM);
        float2 vv = vp2[lane];
        o0 = fmaf(p, vv.x, o0);
        o1 = fmaf(p, vv.y, o1);
    }
    size_t ob = ((size_t)(b * SEQ + s)) * DIM + h * HDIM;
    __nv_bfloat16 h0, l0, h1, l1;
    split1(o0 * inv, h0, l0);
    split1(o1 * inv, h1, l1);
    *reinterpret_cast<uint32_t*>(outh + ob + 2 * lane) = pack_bf16(h0, h1);
    *reinterpret_cast<uint32_t*>(outl + ob + 2 * lane) = pack_bf16(l0, l1);
}

// ---------------- Patchify -> bf16 hi/lo ----------------
__global__ void patchify_kernel(const float* __restrict__ x,
                                __nv_bfloat16* __restrict__ xph, __nv_bfloat16* __restrict__ xpl)
{
    int idx = blockIdx.x * blockDim.x + threadIdx.x;
    const int total = NROWS_P * DIM;
    if (idx >= total) return;
    int e  = idx % DIM;
    int bp = idx / DIM;
    int p  = bp % NPATCH;
    int b  = bp / NPATCH;
    int c  = e / (PATCH * PATCH);
    int r  = e % (PATCH * PATCH);
    int py = r / PATCH, px = r % PATCH;
    int gy = p / GRID,  gx = p % GRID;
    float v = x[(((size_t)b * CHN + c) * IMG + gy * PATCH + py) * IMG + gx * PATCH + px];
    __nv_bfloat16 h, l;
    split1(v, h, l);
    xph[idx] = h;
    xpl[idx] = l;
}

// ---------------- cls rows ----------------
__global__ void cls_kernel(const float* __restrict__ cls, const float* __restrict__ pos,
                           float* __restrict__ hout)
{
    int idx = blockIdx.x * blockDim.x + threadIdx.x;
    if (idx >= BATCH * DIM) return;
    int d = idx % DIM;
    int b = idx / DIM;
    hout[(size_t)(b * SEQ) * DIM + d] = cls[d] + pos[d];
}

// ---------------- host launcher ----------------
extern "C" void kernel_launch(void* const* d_in, const int* in_sizes, int n_in,
                              void* d_out, int out_size)
{
    const float* x        = (const float*)d_in[0];
    const float* patch_w  = (const float*)d_in[1];
    const float* patch_b  = (const float*)d_in[2];
    const float* cls_tok  = (const float*)d_in[3];
    const float* pos_emb  = (const float*)d_in[4];
    const float* qkv_w    = (const float*)d_in[5];
    const float* qkv_b    = (const float*)d_in[6];
    const float* proj_w   = (const float*)d_in[7];
    const float* proj_b   = (const float*)d_in[8];
    const float* ln1_s    = (const float*)d_in[9];
    const float* ln1_b    = (const float*)d_in[10];
    const float* ln2_s    = (const float*)d_in[11];
    const float* ln2_b    = (const float*)d_in[12];
    const float* fc1_w    = (const float*)d_in[13];
    const float* fc1_b    = (const float*)d_in[14];
    const float* fc2_w    = (const float*)d_in[15];
    const float* fc2_b    = (const float*)d_in[16];
    const int*   routes   = (const int*)d_in[17];

    float *hbuf, *qkv;
    __nv_bfloat16 *xnh, *xnl, *atth, *attl, *mlph, *mlpl, *wh, *wl;
    cudaGetSymbolAddress((void**)&hbuf, g_h);
    cudaGetSymbolAddress((void**)&qkv,  g_qkv);
    cudaGetSymbolAddress((void**)&xnh,  g_xnh);
    cudaGetSymbolAddress((void**)&xnl,  g_xnl);
    cudaGetSymbolAddress((void**)&atth, g_atth);
    cudaGetSymbolAddress((void**)&attl, g_attl);
    cudaGetSymbolAddress((void**)&mlph, g_mlph);
    cudaGetSymbolAddress((void**)&mlpl, g_mlpl);
    cudaGetSymbolAddress((void**)&wh,   g_wh);
    cudaGetSymbolAddress((void**)&wl,   g_wl);

    // smem per config
    const int SMEM_64_128  = 2 * (2 * 64 * 80 + 2 * 128 * 80);   // 61440, occ 3
    const int SMEM_64_64   = 2 * (2 * 64 * 80 + 2 * 64 * 80);    // 40960, occ 4
    cudaFuncSetAttribute(hgemm<64, 128, 0, 3>,  cudaFuncAttributeMaxDynamicSharedMemorySize, SMEM_64_128);
    cudaFuncSetAttribute(hgemm<64, 128, 3, 3>,  cudaFuncAttributeMaxDynamicSharedMemorySize, SMEM_64_128);
    cudaFuncSetAttribute(hgemm<64, 64, 1, 4>,   cudaFuncAttributeMaxDynamicSharedMemorySize, SMEM_64_64);
    cudaFuncSetAttribute(hgemm<64, 64, 2, 4>,   cudaFuncAttributeMaxDynamicSharedMemorySize, SMEM_64_64);

    // one-time weight split (single merged launch)
    cvt_all<<<(NW_TOTAL / 4 + 255) / 256, 256>>>(patch_w, qkv_w, proj_w, fc1_w, fc2_w, wh, wl);

    const int rt64  = (NROWS + 63) / 64;     // 25
    const int rt64p = (NROWS_P + 63) / 64;   // 25

    // patch embed: patchify -> GEMM (EPI=3) -> cls rows
    {
        int tot = NROWS_P * DIM;
        patchify_kernel<<<(tot + 255) / 256, 256>>>(x, mlph, mlpl);
        hgemm<64, 128, 3, 3><<<dim3(DIM / 128, rt64p), 128, SMEM_64_128>>>(
            mlph, mlpl, wh + OFF_PATCH, wl + OFF_PATCH, patch_b, pos_emb,
            hbuf, nullptr, nullptr, NROWS_P, DIM, DIM);
        cls_kernel<<<(BATCH * DIM + 255) / 256, 256>>>(cls_tok, pos_emb, hbuf);
    }

    for (int l = 0; l < NLAYER; l++) {
        const size_t oq  = OFF_QKV  + (size_t)l * 3 * DIM * DIM;
        const size_t op  = OFF_PROJ + (size_t)l * DIM * DIM;
        const size_t of1 = OFF_FC1  + (size_t)l * MLPDIM * DIM;
        const size_t of2 = OFF_FC2  + (size_t)l * DIM * MLPDIM;
        const float* qb  = qkv_b  + (size_t)l * 3 * DIM;
        const float* pb  = proj_b + (size_t)l * DIM;
        const float* f1b = fc1_b  + (size_t)l * MLPDIM;
        const float* f2b = fc2_b  + (size_t)l * DIM;

        ln_kernel<<<NROWS, 256>>>(hbuf, ln1_s + (size_t)l * DIM, ln1_b + (size_t)l * DIM,
                                  xnh, xnl);
        // QKV: BM=64/BN=128, occ 3 -> 18x25 = 450 blocks / 444 slots = 1.01 waves
        hgemm<64, 128, 0, 3><<<dim3(3 * DIM / 128, rt64), 128, SMEM_64_128>>>(
            xnh, xnl, wh + oq, wl + oq, qb, nullptr,
            qkv, nullptr, nullptr, NROWS, DIM, 3 * DIM);
        attn_kernel<<<dim3(BATCH * NHEAD, (SEQ + 3) / 4), 128>>>(qkv, routes, atth, attl);
        hgemm<64, 64, 2, 4><<<dim3(DIM / 64, rt64), 128, SMEM_64_64>>>(
            atth, attl, wh + op, wl + op, pb, hbuf,
            hbuf, nullptr, nullptr, NROWS, DIM, DIM);
        ln_kernel<<<NROWS, 256>>>(hbuf, ln2_s + (size_t)l * DIM, ln2_b + (size_t)l * DIM,
                                  xnh, xnl);
        // fc1: BM=64/BN=64, occ 4 -> 48x25 = 1200 blocks / 592 slots
        hgemm<64, 64, 1, 4><<<dim3(MLPDIM / 64, rt64), 128, SMEM_64_64>>>(
            xnh, xnl, wh + of1, wl + of1, f1b, nullptr,
            nullptr, mlph, mlpl, NROWS, DIM, MLPDIM);
        float* outp = (l == NLAYER - 1) ? (float*)d_out : hbuf;
        hgemm<64, 64, 2, 4><<<dim3(DIM / 64, rt64), 128, SMEM_64_64>>>(
            mlph, mlpl, wh + of2, wl + of2, f2b, hbuf,
            outp, nullptr, nullptr, NROWS, MLPDIM, DIM);
    }
}